// round 16
// baseline (speedup 1.0000x reference)
#include <cuda_runtime.h>

#define GN 4096   // N*N
#define TT 168    // T
#define BB 128    // B
#define NN 64     // N
#define PP 128    // P

#define THREADS      512
#define ROWS_PER_BLK 16
#define MV_BLOCKS    (GN / ROWS_PER_BLK)   // 256
#define YB_BATCH     4
#define Y_BLOCKS     (BB / YB_BATCH)       // 32
#define TOTAL_BLK    (Y_BLOCKS + MV_BLOCKS) // 288 blocks @ 512 thr: one wave

#define TT4 (TT / 4)                       // 42 float4 per F row

// Scratch + sync (allocation-free rule: __device__ globals; zero at load,
// self-resetting every replay). NOTE: no d_y — y lives in producer smem.
__device__ float d_v[GN];
__device__ int   d_mv_done;
__device__ int   d_z_done;

__device__ __forceinline__ float dot4(float4 a, float4 b) {
    return a.x * b.x + a.y * b.y + a.z * b.z + a.w * b.w;
}

__device__ __forceinline__ float4 ldcg4(const float4* p) {
    float4 v;
    asm volatile("ld.global.cg.v4.f32 {%0,%1,%2,%3}, [%4];"
                 : "=f"(v.x), "=f"(v.y), "=f"(v.z), "=f"(v.w) : "l"(p));
    return v;
}

__device__ __forceinline__ int ld_flag(const int* p) {
    int v;
    asm volatile("ld.global.cg.b32 %0, [%1];" : "=r"(v) : "l"(p) : "memory");
    return v;
}

// ---------------------------------------------------------------------------
// ONE kernel, 288 blocks x 512 threads (single co-resident wave: 4 blk/SM
// cap by threads -> 592 slots >= 288; y-blocks resident from t=0).
//
//  blocks [0, 32):   y-block, 4 batches: y[b,j] = sum_p x[b,j,p]*alpha[xi],
//                    y kept in SMEM (no global y at all). Then poll
//                    d_mv_done==256 (ld.cg + nanosleep; only 32 parked
//                    blocks = 512 warps, ~11% of slots). On release:
//                    Z[b,i] = sum_j v[i*64+j]*y[b,j] — per thread 8
//                    independent ldcg float4 of L2-hot v + smem y,
//                    pair-shfl, plain store. Tail ~0.5us.
//  blocks [32, 288): matvec, 16 rows/block, warp-per-row, w^2 staged in
//                    smem, g via ldcg, fused F epilogue (R4-proven),
//                    v -> d_v, fence + RED-signal. NEVER waits.
// ---------------------------------------------------------------------------
__global__ void __launch_bounds__(THREADS) k_all(const float* __restrict__ g,
                                                 const float* __restrict__ w,
                                                 const float* __restrict__ alphas,
                                                 const float* __restrict__ x,
                                                 const int*   __restrict__ xi,
                                                 float* __restrict__ Fout,
                                                 float* __restrict__ Zout) {
    __shared__ __align__(16) float ws[GN];       // mv: w^2 | y: ap then free
    __shared__ __align__(16) float sal[TT + 8];
    __shared__ __align__(16) float sy[YB_BATCH * NN];   // y-block: its y slice

    const int blk  = blockIdx.x;
    const int tid  = threadIdx.x;
    const int wid  = tid >> 5;
    const int lane = tid & 31;

    if (blk < Y_BLOCKS) {
        // ---------------- y phase: batches b0 .. b0+3 ----------------
        const int b0 = blk * YB_BATCH;
        float* ap = ws;                      // 4 x 128 = 512 entries
        ap[tid] = alphas[xi[b0 * PP + tid]];
        __syncthreads();

        const int bsel = wid >> 2;           // 0..3
        const int j00  = wid & 3;
        const float* __restrict__ apb = ap + bsel * PP;
        #pragma unroll
        for (int j = j00; j < NN; j += 4) {
            const float* __restrict__ xr =
                x + ((size_t)(b0 + bsel) * NN + j) * PP;
            float s = xr[lane]      * apb[lane]
                    + xr[lane + 32] * apb[lane + 32]
                    + xr[lane + 64] * apb[lane + 64]
                    + xr[lane + 96] * apb[lane + 96];
            #pragma unroll
            for (int o = 16; o > 0; o >>= 1)
                s += __shfl_xor_sync(0xffffffffu, s, o);
            if (lane == 0) sy[bsel * NN + j] = s;     // y stays in smem
        }
        __syncthreads();

        // ---------------- gate: wait for all matvec blocks ----------------
        if (tid == 0) {
            while (ld_flag(&d_mv_done) < MV_BLOCKS)
                __nanosleep(128);
            __threadfence();                 // acquire
        }
        __syncthreads();

        // ---------------- Z phase: 4 batches x 64 outputs ----------------
        // thread: bq = tid>>7 (batch), r = tid&127, i = r>>1, h = r&1.
        {
            const int bq = tid >> 7;
            const int r  = tid & 127;
            const int i  = r >> 1;
            const int h  = r & 1;
            const float4* __restrict__ v4 =
                reinterpret_cast<const float4*>(d_v) + i * 16 + h * 8;
            const float4* __restrict__ y4 =
                reinterpret_cast<const float4*>(sy + bq * NN + h * 32);

            float4 a0 = ldcg4(v4);     float4 a1 = ldcg4(v4 + 1);
            float4 a2 = ldcg4(v4 + 2); float4 a3 = ldcg4(v4 + 3);
            float4 a4 = ldcg4(v4 + 4); float4 a5 = ldcg4(v4 + 5);
            float4 a6 = ldcg4(v4 + 6); float4 a7 = ldcg4(v4 + 7);

            float s = dot4(a0, y4[0]) + dot4(a1, y4[1])
                    + dot4(a2, y4[2]) + dot4(a3, y4[3])
                    + dot4(a4, y4[4]) + dot4(a5, y4[5])
                    + dot4(a6, y4[6]) + dot4(a7, y4[7]);
            s += __shfl_xor_sync(0xffffffffu, s, 1);  // combine h=0,1
            if (h == 0)
                Zout[(b0 + bq) * NN + i] = s;         // unique writer
        }

        // ---------------- reset counters for next replay ----------------
        __syncthreads();
        if (tid == 0) {
            if (atomicAdd(&d_z_done, 1) == Y_BLOCKS - 1) {
                atomicExch(&d_z_done, 0);
                atomicExch(&d_mv_done, 0);
            }
        }
        return;
    }

    // ---------------- matvec block (NEVER waits) ----------------
    const int mvb = blk - Y_BLOCKS;

    // stage w^2 (16 KB) + alphas into smem
    const float4* __restrict__ w4g = reinterpret_cast<const float4*>(w);
    float4* ws4 = reinterpret_cast<float4*>(ws);
    #pragma unroll
    for (int k = 0; k < 2; k++) {
        float4 t = w4g[tid + k * 512];
        t.x *= t.x; t.y *= t.y; t.z *= t.z; t.w *= t.w;
        ws4[tid + k * 512] = t;
    }
    if (tid < TT) sal[tid] = alphas[tid];
    __syncthreads();

    // warp-per-row dot product (row = mvb*16 + wid)
    const int row = mvb * ROWS_PER_BLK + wid;
    const float4* __restrict__ g4 =
        reinterpret_cast<const float4*>(g + (size_t)row * GN);

    float acc0 = 0.f, acc1 = 0.f, acc2 = 0.f, acc3 = 0.f;
    #pragma unroll
    for (int c = 0; c < 8; c++) {
        const int base = c * 128 + lane;              // float4 units
        float4 a0 = ldcg4(g4 + base);
        float4 a1 = ldcg4(g4 + base + 32);
        float4 a2 = ldcg4(g4 + base + 64);
        float4 a3 = ldcg4(g4 + base + 96);
        float4 b0 = ws4[base];      float4 b1 = ws4[base + 32];
        float4 b2 = ws4[base + 64]; float4 b3 = ws4[base + 96];
        acc0 += dot4(a0, b0);
        acc1 += dot4(a1, b1);
        acc2 += dot4(a2, b2);
        acc3 += dot4(a3, b3);
    }
    float s = (acc0 + acc1) + (acc2 + acc3);
    #pragma unroll
    for (int o = 16; o > 0; o >>= 1)
        s += __shfl_xor_sync(0xffffffffu, s, o);       // all lanes get sum

    if (lane == 0) d_v[row] = s;

    // F epilogue (vectorized, 42 STG.128 per row)
    const float4* __restrict__ sal4 = reinterpret_cast<const float4*>(sal);
    float4* __restrict__ Fr4 =
        reinterpret_cast<float4*>(Fout + (size_t)row * TT);
    #pragma unroll
    for (int t = lane; t < TT4; t += 32) {
        float4 a = sal4[t];
        a.x *= s; a.y *= s; a.z *= s; a.w *= s;
        Fr4[t] = a;
    }

    // publish v + signal (RED: result discarded -> no atomic-ALU hotspot)
    __syncthreads();
    if (tid == 0) {
        __threadfence();
        atomicAdd(&d_mv_done, 1);
    }
}

// ---------------------------------------------------------------------------
extern "C" void kernel_launch(void* const* d_in, const int* in_sizes, int n_in,
                              void* d_out, int out_size) {
    const float* x      = (const float*)d_in[0];   // [B, N, P]
    const int*   xi     = (const int*)  d_in[1];   // [B, P]
    const float* g      = (const float*)d_in[2];   // [N*N, N*N]
    const float* w      = (const float*)d_in[3];   // [N*N, 1]
    const float* alphas = (const float*)d_in[4];   // [1, T]

    float* out = (float*)d_out;
    float* Z = out;               // [B, N]   = 8192
    float* F = out + BB * NN;     // [N*N, T] = 688128

    k_all<<<TOTAL_BLK, THREADS>>>(g, w, alphas, x, xi, F, Z);
}